// round 1
// baseline (speedup 1.0000x reference)
#include <cuda_runtime.h>

// Problem constants
#define NPTS   16384           // N*P
#define KNB    16              // K neighbors
#define C_IN   128
#define C_MID  64
#define C_OUT  256
#define C_CAT  192             // C_MID + C_IN
#define KK     256             // K*K
#define CD     384             // C_CAT * DM
#define EPSBN  1e-5f

// ---------------- device scratch (no allocations allowed) ----------------
__device__ float g_pl  [NPTS * KNB * 3];     // pts_local            (3 MB)
__device__ float g_lift[NPTS * KNB * C_MID]; // lifted features      (67 MB)
__device__ float g_x   [NPTS * KK];          // X transform          (16.7 MB)
__device__ float g_dw  [NPTS * CD];          // depthwise output     (25 MB)
__device__ float g_pre [NPTS * C_OUT];       // pre-BN relu output   (16.7 MB)
__device__ float g_cvt [48 * KK];            // cv_w transposed
__device__ float g_pwt [CD * C_OUT];         // pw_w transposed
__device__ float g_part[256 * 2 * C_OUT];    // per-block BN partials
__device__ float g_stats[2 * C_OUT];         // mean, inv_std

// ---------------- k0: transpose small weights for coalesced B reads ------
__global__ void k0_prep(const float* __restrict__ cv_w,
                        const float* __restrict__ pw_w) {
    int tot = 48 * KK + CD * C_OUT;
    for (int idx = blockIdx.x * blockDim.x + threadIdx.x; idx < tot;
         idx += gridDim.x * blockDim.x) {
        if (idx < 48 * KK) {
            int j = idx >> 8, o = idx & 255;      // j = k*3 + d
            int k = j / 3, d = j - k * 3;
            g_cvt[idx] = cv_w[o * 48 + d * 16 + k];
        } else {
            int i = idx - 48 * KK;
            int j = i >> 8, o = i & 255;
            g_pwt[i] = pw_w[o * CD + j];
        }
    }
}

// ---------------- k1: pts_local + lift MLP (3->64 relu ->64 relu) --------
// 8 points / block, 256 threads. rows = 8*16 = 128.
__global__ void k1_lift(const float* __restrict__ rep,
                        const float* __restrict__ pts,
                        const float* __restrict__ w1, const float* __restrict__ b1,
                        const float* __restrict__ w2, const float* __restrict__ b2) {
    __shared__ float s_pl[8 * KNB * 3];            // 384
    __shared__ float s_h[128 * C_MID];             // 8192 floats = 32KB
    int tid = threadIdx.x;
    int base = blockIdx.x * 384;                   // float offset into pts

    for (int idx = tid; idx < 384; idx += 256) {
        int p = blockIdx.x * 8 + idx / 48;
        int d = idx % 3;
        float v = pts[base + idx] - rep[p * 3 + d];
        s_pl[idx] = v;
        g_pl[base + idx] = v;
    }
    __syncthreads();

    // h = relu(pl @ w1 + b1): 128 rows x 64 cols
    for (int e = tid; e < 128 * 64; e += 256) {
        int row = e >> 6, o = e & 63;
        float v = __ldg(b1 + o);
        v += s_pl[row * 3 + 0] * __ldg(w1 + o);
        v += s_pl[row * 3 + 1] * __ldg(w1 + 64 + o);
        v += s_pl[row * 3 + 2] * __ldg(w1 + 128 + o);
        s_h[e] = fmaxf(v, 0.f);
    }
    __syncthreads();

    // lift = relu(h @ w2 + b2): 128x64x64, micro-tile 8 rows x 4 cols
    int cg = tid & 15, rg = tid >> 4;
    int r0 = rg * 8, c0 = cg * 4;
    float acc[8][4];
    float4 bb = __ldg((const float4*)(b2 + c0));
#pragma unroll
    for (int r = 0; r < 8; r++) {
        acc[r][0] = bb.x; acc[r][1] = bb.y; acc[r][2] = bb.z; acc[r][3] = bb.w;
    }
#pragma unroll 4
    for (int j = 0; j < 64; j++) {
        float4 w = __ldg((const float4*)(w2 + j * 64 + c0));
#pragma unroll
        for (int r = 0; r < 8; r++) {
            float a = s_h[(r0 + r) * 64 + j];
            acc[r][0] += a * w.x; acc[r][1] += a * w.y;
            acc[r][2] += a * w.z; acc[r][3] += a * w.w;
        }
    }
    int growbase = blockIdx.x * 128;
#pragma unroll
    for (int r = 0; r < 8; r++) {
        float4 v;
        v.x = fmaxf(acc[r][0], 0.f); v.y = fmaxf(acc[r][1], 0.f);
        v.z = fmaxf(acc[r][2], 0.f); v.w = fmaxf(acc[r][3], 0.f);
        *(float4*)(g_lift + (growbase + r0 + r) * 64 + c0) = v;
    }
}

// ---------------- k2: fused X-transform (48->256 relu ->256 relu ->256) --
// 16 points / block, 256 threads, micro-tile 4 rows x 4 cols per stage.
template <int KDIM, int LDA, bool RELU, bool TOSMEM>
__device__ __forceinline__ void gemm_stage(const float* sA,
                                           const float* __restrict__ W,
                                           const float* __restrict__ bias,
                                           float* outp, int ldo,
                                           int r0, int c0) {
    float acc[4][4];
    float4 bb = __ldg((const float4*)(bias + c0));
#pragma unroll
    for (int r = 0; r < 4; r++) {
        acc[r][0] = bb.x; acc[r][1] = bb.y; acc[r][2] = bb.z; acc[r][3] = bb.w;
    }
#pragma unroll 4
    for (int j = 0; j < KDIM; j++) {
        float4 w = __ldg((const float4*)(W + j * 256 + c0));
#pragma unroll
        for (int r = 0; r < 4; r++) {
            float a = sA[(r0 + r) * LDA + j];
            acc[r][0] += a * w.x; acc[r][1] += a * w.y;
            acc[r][2] += a * w.z; acc[r][3] += a * w.w;
        }
    }
#pragma unroll
    for (int r = 0; r < 4; r++) {
        float4 v;
        if (RELU) {
            v.x = fmaxf(acc[r][0], 0.f); v.y = fmaxf(acc[r][1], 0.f);
            v.z = fmaxf(acc[r][2], 0.f); v.w = fmaxf(acc[r][3], 0.f);
        } else {
            v.x = acc[r][0]; v.y = acc[r][1]; v.z = acc[r][2]; v.w = acc[r][3];
        }
        *(float4*)(outp + (r0 + r) * ldo + c0) = v;
    }
}

__global__ void k2_xtrans(const float* __restrict__ cv_b,
                          const float* __restrict__ x1w, const float* __restrict__ x1b,
                          const float* __restrict__ x2w, const float* __restrict__ x2b) {
    __shared__ __align__(16) float s_a[16 * 48];    // 3KB
    __shared__ __align__(16) float s_x0[16 * KK];   // 16KB
    __shared__ __align__(16) float s_x1[16 * KK];   // 16KB
    int tid = threadIdx.x;
    int pbase = blockIdx.x * 16;

    for (int idx = tid; idx < 16 * 48; idx += 256)
        s_a[idx] = g_pl[pbase * 48 + idx];
    __syncthreads();

    int cg = tid & 63, rg = tid >> 6;   // 4 row-groups of 4, 64 col-groups of 4
    int r0 = rg * 4, c0 = cg * 4;

    gemm_stage<48, 48, true, true>(s_a, g_cvt, cv_b, s_x0, KK, r0, c0);
    __syncthreads();
    gemm_stage<256, 256, true, true>(s_x0, x1w, x1b, s_x1, KK, r0, c0);
    __syncthreads();
    gemm_stage<256, 256, false, false>(s_x1, x2w, x2b, g_x + pbase * KK, KK, r0, c0);
}

// ---------------- k3: apply 16x16 X + depthwise conv ---------------------
// 4 points / block, 192 threads (one per concat channel c).
__global__ void k3_mid(const float* __restrict__ fts,
                       const float* __restrict__ dww,
                       const float* __restrict__ dwb) {
    __shared__ float s_X[KK];
    int tid = threadIdx.x;   // 0..191 = channel c
    for (int pp = 0; pp < 4; pp++) {
        int p = blockIdx.x * 4 + pp;
        __syncthreads();
        for (int i = tid; i < KK; i += 192) s_X[i] = g_x[p * KK + i];
        __syncthreads();

        float fcat[KNB];
        if (tid < C_MID) {
#pragma unroll
            for (int j = 0; j < KNB; j++)
                fcat[j] = g_lift[(p * KNB + j) * C_MID + tid];
        } else {
            int cc = tid - C_MID;
#pragma unroll
            for (int j = 0; j < KNB; j++)
                fcat[j] = __ldg(fts + (p * KNB + j) * C_IN + cc);
        }

        float fx[KNB];
#pragma unroll
        for (int i = 0; i < KNB; i++) {
            float s = 0.f;
#pragma unroll
            for (int j = 0; j < KNB; j++) s += s_X[i * KNB + j] * fcat[j];
            fx[i] = s;
        }
#pragma unroll
        for (int m = 0; m < 2; m++) {
            float s = __ldg(dwb + tid * 2 + m);
#pragma unroll
            for (int k = 0; k < KNB; k++)
                s += fx[k] * __ldg(dww + tid * 32 + m * 16 + k);
            g_dw[p * CD + tid * 2 + m] = s;
        }
    }
}

// ---------------- k4: pointwise GEMM 16384x384x256 + relu + BN partials --
// 64 points / block, 256 threads, micro-tile 8x8.
__global__ void k4_pw() {
    __shared__ float s_a[64 * 64];            // 16KB
    __shared__ float s_red[2 * 8 * C_OUT];    // 16KB
    int tid = threadIdx.x;
    int cg = tid & 31, rg = tid >> 5;
    int r0 = rg * 8, c0 = cg * 8;
    int rowbase = blockIdx.x * 64;

    float acc[8][8];
#pragma unroll
    for (int r = 0; r < 8; r++)
#pragma unroll
        for (int c = 0; c < 8; c++) acc[r][c] = 0.f;

    for (int jc = 0; jc < 6; jc++) {
        __syncthreads();
        for (int idx = tid; idx < 4096; idx += 256) {
            int r = idx >> 6, j = idx & 63;
            s_a[idx] = g_dw[(rowbase + r) * CD + jc * 64 + j];
        }
        __syncthreads();
#pragma unroll 4
        for (int j = 0; j < 64; j++) {
            const float* wp = g_pwt + (jc * 64 + j) * 256 + c0;
            float4 w0 = __ldg((const float4*)wp);
            float4 w1 = __ldg((const float4*)(wp + 4));
#pragma unroll
            for (int r = 0; r < 8; r++) {
                float a = s_a[(r0 + r) * 64 + j];
                acc[r][0] += a * w0.x; acc[r][1] += a * w0.y;
                acc[r][2] += a * w0.z; acc[r][3] += a * w0.w;
                acc[r][4] += a * w1.x; acc[r][5] += a * w1.y;
                acc[r][6] += a * w1.z; acc[r][7] += a * w1.w;
            }
        }
    }

    // relu + store + deterministic per-block BN partials
    float csum[8], csq[8];
#pragma unroll
    for (int c = 0; c < 8; c++) { csum[c] = 0.f; csq[c] = 0.f; }
#pragma unroll
    for (int r = 0; r < 8; r++) {
#pragma unroll
        for (int c = 0; c < 8; c++) {
            float v = fmaxf(acc[r][c], 0.f);
            acc[r][c] = v;
            csum[c] += v; csq[c] += v * v;
        }
        float4 v0 = make_float4(acc[r][0], acc[r][1], acc[r][2], acc[r][3]);
        float4 v1 = make_float4(acc[r][4], acc[r][5], acc[r][6], acc[r][7]);
        float* op = g_pre + (rowbase + r0 + r) * C_OUT + c0;
        *(float4*)op = v0;
        *(float4*)(op + 4) = v1;
    }
#pragma unroll
    for (int c = 0; c < 8; c++) {
        s_red[rg * C_OUT + c0 + c] = csum[c];
        s_red[8 * C_OUT + rg * C_OUT + c0 + c] = csq[c];
    }
    __syncthreads();
    // 256 threads -> one channel each, fixed-order reduce (deterministic)
    float s = 0.f, s2 = 0.f;
#pragma unroll
    for (int g = 0; g < 8; g++) {
        s  += s_red[g * C_OUT + tid];
        s2 += s_red[8 * C_OUT + g * C_OUT + tid];
    }
    g_part[blockIdx.x * 512 + tid] = s;
    g_part[blockIdx.x * 512 + 256 + tid] = s2;
}

// ---------------- k5: final BN stats -------------------------------------
__global__ void k5_stats() {
    int o = threadIdx.x;
    float s = 0.f, s2 = 0.f;
    for (int b = 0; b < 256; b++) {
        s  += g_part[b * 512 + o];
        s2 += g_part[b * 512 + 256 + o];
    }
    float mean = s * (1.f / (float)NPTS);
    float var  = s2 * (1.f / (float)NPTS) - mean * mean;
    g_stats[o] = mean;
    g_stats[256 + o] = rsqrtf(var + EPSBN);
}

// ---------------- k6: normalize ------------------------------------------
__global__ void k6_norm(const float* __restrict__ bn_g,
                        const float* __restrict__ bn_b,
                        float* __restrict__ out) {
    int o = threadIdx.x;
    int idx = blockIdx.x * 256 + o;
    float v = g_pre[idx];
    out[idx] = (v - g_stats[o]) * g_stats[256 + o] * __ldg(bn_g + o) + __ldg(bn_b + o);
}

// ---------------- launch ---------------------------------------------------
extern "C" void kernel_launch(void* const* d_in, const int* in_sizes, int n_in,
                              void* d_out, int out_size) {
    const float* rep = (const float*)d_in[0];
    const float* pts = (const float*)d_in[1];
    const float* fts = (const float*)d_in[2];
    const float* d1w = (const float*)d_in[3];
    const float* d1b = (const float*)d_in[4];
    const float* d2w = (const float*)d_in[5];
    const float* d2b = (const float*)d_in[6];
    const float* cvw = (const float*)d_in[7];
    const float* cvb = (const float*)d_in[8];
    const float* x1w = (const float*)d_in[9];
    const float* x1b = (const float*)d_in[10];
    const float* x2w = (const float*)d_in[11];
    const float* x2b = (const float*)d_in[12];
    const float* dww = (const float*)d_in[13];
    const float* dwb = (const float*)d_in[14];
    const float* pww = (const float*)d_in[15];
    const float* bng = (const float*)d_in[16];
    const float* bnb = (const float*)d_in[17];
    float* out = (float*)d_out;

    k0_prep<<<128, 256>>>(cvw, pww);
    k1_lift<<<NPTS / 8, 256>>>(rep, pts, d1w, d1b, d2w, d2b);
    k2_xtrans<<<NPTS / 16, 256>>>(cvb, x1w, x1b, x2w, x2b);
    k3_mid<<<NPTS / 4, 192>>>(fts, dww, dwb);
    k4_pw<<<NPTS / 64, 256>>>();
    k5_stats<<<1, 256>>>();
    k6_norm<<<NPTS, 256>>>(bng, bnb, out);
}

// round 2
// speedup vs baseline: 1.4019x; 1.4019x over previous
#include <cuda_runtime.h>

// Problem constants
#define NPTS   16384           // N*P
#define KNB    16              // K neighbors
#define C_IN   128
#define C_MID  64
#define C_OUT  256
#define C_CAT  192             // C_MID + C_IN
#define KK     256             // K*K
#define CD     384             // C_CAT * DM
#define EPSBN  1e-5f

// ---------------- device scratch (no allocations allowed) ----------------
__device__ float g_pl  [NPTS * KNB * 3];     // pts_local
__device__ float g_lift[NPTS * KNB * C_MID]; // lifted features
__device__ float g_x   [NPTS * KK];          // X transform
__device__ float g_dw  [NPTS * CD];          // depthwise output
__device__ float g_pre [NPTS * C_OUT];       // pre-BN relu output
__device__ float g_cvt [48 * KK];            // cv_w transposed
__device__ float g_pwt [CD * C_OUT];         // pw_w transposed
__device__ float g_part[256 * 2 * C_OUT];    // per-block BN partials
__device__ float g_stats[2 * C_OUT];         // mean, inv_std

// ---------------- packed f32x2 helpers -----------------------------------
__device__ __forceinline__ void fma2(unsigned long long& d,
                                     unsigned long long a,
                                     unsigned long long b) {
    asm("fma.rn.f32x2 %0, %1, %2, %0;" : "+l"(d) : "l"(a), "l"(b));
}
__device__ __forceinline__ unsigned long long dupf(float v) {
    unsigned u = __float_as_uint(v);
    return ((unsigned long long)u << 32) | (unsigned long long)u;
}
__device__ __forceinline__ float lo32(unsigned long long v) {
    return __uint_as_float((unsigned)v);
}
__device__ __forceinline__ float hi32(unsigned long long v) {
    return __uint_as_float((unsigned)(v >> 32));
}

// ---------------- k0: transpose small weights for coalesced B reads ------
__global__ void k0_prep(const float* __restrict__ cv_w,
                        const float* __restrict__ pw_w) {
    int tot = 48 * KK + CD * C_OUT;
    for (int idx = blockIdx.x * blockDim.x + threadIdx.x; idx < tot;
         idx += gridDim.x * blockDim.x) {
        if (idx < 48 * KK) {
            int j = idx >> 8, o = idx & 255;      // j = k*3 + d
            int k = j / 3, d = j - k * 3;
            g_cvt[idx] = cv_w[o * 48 + d * 16 + k];
        } else {
            int i = idx - 48 * KK;
            int j = i >> 8, o = i & 255;
            g_pwt[i] = pw_w[o * CD + j];
        }
    }
}

// ---------------- k1: pts_local + lift MLP (3->64 relu ->64 relu) --------
// 8 points / block, 256 threads. rows = 8*16 = 128.
__global__ void k1_lift(const float* __restrict__ rep,
                        const float* __restrict__ pts,
                        const float* __restrict__ w1, const float* __restrict__ b1,
                        const float* __restrict__ w2, const float* __restrict__ b2) {
    __shared__ float s_pl[8 * KNB * 3];
    __shared__ float s_h[128 * C_MID];
    int tid = threadIdx.x;
    int base = blockIdx.x * 384;

    for (int idx = tid; idx < 384; idx += 256) {
        int p = blockIdx.x * 8 + idx / 48;
        int d = idx % 3;
        float v = pts[base + idx] - rep[p * 3 + d];
        s_pl[idx] = v;
        g_pl[base + idx] = v;
    }
    __syncthreads();

    for (int e = tid; e < 128 * 64; e += 256) {
        int row = e >> 6, o = e & 63;
        float v = __ldg(b1 + o);
        v += s_pl[row * 3 + 0] * __ldg(w1 + o);
        v += s_pl[row * 3 + 1] * __ldg(w1 + 64 + o);
        v += s_pl[row * 3 + 2] * __ldg(w1 + 128 + o);
        s_h[e] = fmaxf(v, 0.f);
    }
    __syncthreads();

    int cg = tid & 15, rg = tid >> 4;
    int r0 = rg * 8, c0 = cg * 4;
    float acc[8][4];
    float4 bb = __ldg((const float4*)(b2 + c0));
#pragma unroll
    for (int r = 0; r < 8; r++) {
        acc[r][0] = bb.x; acc[r][1] = bb.y; acc[r][2] = bb.z; acc[r][3] = bb.w;
    }
#pragma unroll 4
    for (int j = 0; j < 64; j++) {
        float4 w = __ldg((const float4*)(w2 + j * 64 + c0));
#pragma unroll
        for (int r = 0; r < 8; r++) {
            float a = s_h[(r0 + r) * 64 + j];
            acc[r][0] += a * w.x; acc[r][1] += a * w.y;
            acc[r][2] += a * w.z; acc[r][3] += a * w.w;
        }
    }
    int growbase = blockIdx.x * 128;
#pragma unroll
    for (int r = 0; r < 8; r++) {
        float4 v;
        v.x = fmaxf(acc[r][0], 0.f); v.y = fmaxf(acc[r][1], 0.f);
        v.z = fmaxf(acc[r][2], 0.f); v.w = fmaxf(acc[r][3], 0.f);
        *(float4*)(g_lift + (growbase + r0 + r) * 64 + c0) = v;
    }
}

// ---------------- k2: fused X-transform with packed f32x2 FMA ------------
// 8 points / block, 256 threads, 2 rows x 4 cols per thread.
// Activations stored duplicated ({v,v} u64) so A operand is one LDS.64.
#define K2P 8

template<int KD, bool RELU, bool TOGLOBAL>
__device__ __forceinline__ void k2_stage(const unsigned long long* sA,
                                         const float* __restrict__ W,
                                         const float* __restrict__ bias,
                                         unsigned long long* sOut, float* gOut,
                                         int r0, int c0) {
    unsigned long long acc00, acc01, acc10, acc11;
    {
        ulonglong2 bb = *(const ulonglong2*)(bias + c0);
        acc00 = bb.x; acc01 = bb.y;
        acc10 = bb.x; acc11 = bb.y;
    }
#pragma unroll 4
    for (int j = 0; j < KD; j++) {
        ulonglong2 w = *(const ulonglong2*)(W + j * 256 + c0);
        unsigned long long a0 = sA[(r0 + 0) * KD + j];
        unsigned long long a1 = sA[(r0 + 1) * KD + j];
        fma2(acc00, a0, w.x); fma2(acc01, a0, w.y);
        fma2(acc10, a1, w.x); fma2(acc11, a1, w.y);
    }
#pragma unroll
    for (int r = 0; r < 2; r++) {
        unsigned long long p0 = r ? acc10 : acc00;
        unsigned long long p1 = r ? acc11 : acc01;
        float v0 = lo32(p0), v1 = hi32(p0), v2 = lo32(p1), v3 = hi32(p1);
        if (RELU) {
            v0 = fmaxf(v0, 0.f); v1 = fmaxf(v1, 0.f);
            v2 = fmaxf(v2, 0.f); v3 = fmaxf(v3, 0.f);
        }
        if (TOGLOBAL) {
            *(float4*)(gOut + (r0 + r) * 256 + c0) = make_float4(v0, v1, v2, v3);
        } else {
            unsigned long long* op = sOut + (r0 + r) * 256 + c0;
            op[0] = dupf(v0); op[1] = dupf(v1); op[2] = dupf(v2); op[3] = dupf(v3);
        }
    }
}

__global__ void k2_xtrans(const float* __restrict__ cv_b,
                          const float* __restrict__ x1w, const float* __restrict__ x1b,
                          const float* __restrict__ x2w, const float* __restrict__ x2b) {
    __shared__ unsigned long long s_a[K2P * 48];          // 3 KB
    __shared__ unsigned long long s_b0[K2P * 256];        // 16 KB
    __shared__ unsigned long long s_b1[K2P * 256];        // 16 KB
    int tid = threadIdx.x;
    int pbase = blockIdx.x * K2P;

    for (int idx = tid; idx < K2P * 48; idx += 256)
        s_a[idx] = dupf(g_pl[pbase * 48 + idx]);
    __syncthreads();

    int cg = tid & 63, rg = tid >> 6;   // 4 row-groups (2 rows each), 64 col-groups
    int r0 = rg * 2, c0 = cg * 4;

    k2_stage<48, true, false>(s_a, g_cvt, cv_b, s_b0, (float*)0, r0, c0);
    __syncthreads();
    k2_stage<256, true, false>(s_b0, x1w, x1b, s_b1, (float*)0, r0, c0);
    __syncthreads();
    k2_stage<256, false, true>(s_b1, x2w, x2b, (unsigned long long*)0,
                               g_x + pbase * KK, r0, c0);
}

// ---------------- k3: apply 16x16 X + depthwise conv (rewritten) ---------
// 8 points / block, 192 threads (one per concat channel c).
// dw weights: coalesced global load -> padded-transpose smem -> registers.
__global__ void k3_mid(const float* __restrict__ fts,
                       const float* __restrict__ dww,
                       const float* __restrict__ dwb) {
    __shared__ float s_wt[32 * 193];               // ~24.7 KB padded transpose
    __shared__ __align__(16) float s_X[KK];
    int tid = threadIdx.x;

    // stage weights: global read coalesced, smem write conflict-free (pad 193)
    for (int idx = tid; idx < 192 * 32; idx += 192) {
        int c = idx >> 5, i = idx & 31;            // i = m*16 + k
        s_wt[i * 193 + c] = dww[idx];
    }
    __syncthreads();
    float wreg[32];
#pragma unroll
    for (int i = 0; i < 32; i++) wreg[i] = s_wt[i * 193 + tid];
    float b0 = __ldg(dwb + 2 * tid), b1 = __ldg(dwb + 2 * tid + 1);

    for (int pp = 0; pp < 8; pp++) {
        int p = blockIdx.x * 8 + pp;
        __syncthreads();
        for (int i = tid; i < KK; i += 192) s_X[i] = g_x[p * KK + i];
        __syncthreads();

        float fcat[KNB];
        if (tid < C_MID) {
#pragma unroll
            for (int j = 0; j < KNB; j++)
                fcat[j] = g_lift[(p * KNB + j) * C_MID + tid];
        } else {
            int cc = tid - C_MID;
#pragma unroll
            for (int j = 0; j < KNB; j++)
                fcat[j] = __ldg(fts + (p * KNB + j) * C_IN + cc);
        }

        float a0 = b0, a1 = b1;
        const float4* X4 = (const float4*)s_X;
#pragma unroll
        for (int i = 0; i < KNB; i++) {
            float s = 0.f;
#pragma unroll
            for (int q = 0; q < 4; q++) {
                float4 x = X4[i * 4 + q];
                s += x.x * fcat[q * 4 + 0] + x.y * fcat[q * 4 + 1]
                   + x.z * fcat[q * 4 + 2] + x.w * fcat[q * 4 + 3];
            }
            a0 += s * wreg[i];
            a1 += s * wreg[16 + i];
        }
        *(float2*)(g_dw + p * CD + 2 * tid) = make_float2(a0, a1);
    }
}

// ---------------- k4: pointwise GEMM 16384x384x256 + relu + BN partials --
__global__ void k4_pw() {
    __shared__ float s_a[64 * 64];
    __shared__ float s_red[2 * 8 * C_OUT];
    int tid = threadIdx.x;
    int cg = tid & 31, rg = tid >> 5;
    int r0 = rg * 8, c0 = cg * 8;
    int rowbase = blockIdx.x * 64;

    float acc[8][8];
#pragma unroll
    for (int r = 0; r < 8; r++)
#pragma unroll
        for (int c = 0; c < 8; c++) acc[r][c] = 0.f;

    for (int jc = 0; jc < 6; jc++) {
        __syncthreads();
        for (int idx = tid; idx < 4096; idx += 256) {
            int r = idx >> 6, j = idx & 63;
            s_a[idx] = g_dw[(rowbase + r) * CD + jc * 64 + j];
        }
        __syncthreads();
#pragma unroll 4
        for (int j = 0; j < 64; j++) {
            const float* wp = g_pwt + (jc * 64 + j) * 256 + c0;
            float4 w0 = __ldg((const float4*)wp);
            float4 w1 = __ldg((const float4*)(wp + 4));
#pragma unroll
            for (int r = 0; r < 8; r++) {
                float a = s_a[(r0 + r) * 64 + j];
                acc[r][0] += a * w0.x; acc[r][1] += a * w0.y;
                acc[r][2] += a * w0.z; acc[r][3] += a * w0.w;
                acc[r][4] += a * w1.x; acc[r][5] += a * w1.y;
                acc[r][6] += a * w1.z; acc[r][7] += a * w1.w;
            }
        }
    }

    float csum[8], csq[8];
#pragma unroll
    for (int c = 0; c < 8; c++) { csum[c] = 0.f; csq[c] = 0.f; }
#pragma unroll
    for (int r = 0; r < 8; r++) {
#pragma unroll
        for (int c = 0; c < 8; c++) {
            float v = fmaxf(acc[r][c], 0.f);
            acc[r][c] = v;
            csum[c] += v; csq[c] += v * v;
        }
        float4 v0 = make_float4(acc[r][0], acc[r][1], acc[r][2], acc[r][3]);
        float4 v1 = make_float4(acc[r][4], acc[r][5], acc[r][6], acc[r][7]);
        float* op = g_pre + (rowbase + r0 + r) * C_OUT + c0;
        *(float4*)op = v0;
        *(float4*)(op + 4) = v1;
    }
#pragma unroll
    for (int c = 0; c < 8; c++) {
        s_red[rg * C_OUT + c0 + c] = csum[c];
        s_red[8 * C_OUT + rg * C_OUT + c0 + c] = csq[c];
    }
    __syncthreads();
    float s = 0.f, s2 = 0.f;
#pragma unroll
    for (int g = 0; g < 8; g++) {
        s  += s_red[g * C_OUT + tid];
        s2 += s_red[8 * C_OUT + g * C_OUT + tid];
    }
    g_part[blockIdx.x * 512 + tid] = s;
    g_part[blockIdx.x * 512 + 256 + tid] = s2;
}

// ---------------- k5: final BN stats -------------------------------------
__global__ void k5_stats() {
    int o = threadIdx.x;
    float s = 0.f, s2 = 0.f;
    for (int b = 0; b < 256; b++) {
        s  += g_part[b * 512 + o];
        s2 += g_part[b * 512 + 256 + o];
    }
    float mean = s * (1.f / (float)NPTS);
    float var  = s2 * (1.f / (float)NPTS) - mean * mean;
    g_stats[o] = mean;
    g_stats[256 + o] = rsqrtf(var + EPSBN);
}

// ---------------- k6: normalize (8 rows / block) -------------------------
__global__ void k6_norm(const float* __restrict__ bn_g,
                        const float* __restrict__ bn_b,
                        float* __restrict__ out) {
    int o = threadIdx.x;
    int p0 = blockIdx.x * 8;
    float mean = g_stats[o], inv = g_stats[256 + o];
    float g = __ldg(bn_g + o) * inv, b = __ldg(bn_b + o);
#pragma unroll
    for (int r = 0; r < 8; r++) {
        int idx = (p0 + r) * 256 + o;
        out[idx] = (g_pre[idx] - mean) * g + b;
    }
}

// ---------------- launch ---------------------------------------------------
extern "C" void kernel_launch(void* const* d_in, const int* in_sizes, int n_in,
                              void* d_out, int out_size) {
    const float* rep = (const float*)d_in[0];
    const float* pts = (const float*)d_in[1];
    const float* fts = (const float*)d_in[2];
    const float* d1w = (const float*)d_in[3];
    const float* d1b = (const float*)d_in[4];
    const float* d2w = (const float*)d_in[5];
    const float* d2b = (const float*)d_in[6];
    const float* cvw = (const float*)d_in[7];
    const float* cvb = (const float*)d_in[8];
    const float* x1w = (const float*)d_in[9];
    const float* x1b = (const float*)d_in[10];
    const float* x2w = (const float*)d_in[11];
    const float* x2b = (const float*)d_in[12];
    const float* dww = (const float*)d_in[13];
    const float* dwb = (const float*)d_in[14];
    const float* pww = (const float*)d_in[15];
    const float* bng = (const float*)d_in[16];
    const float* bnb = (const float*)d_in[17];
    float* out = (float*)d_out;

    k0_prep<<<128, 256>>>(cvw, pww);
    k1_lift<<<NPTS / 8, 256>>>(rep, pts, d1w, d1b, d2w, d2b);
    k2_xtrans<<<NPTS / K2P, 256>>>(cvb, x1w, x1b, x2w, x2b);
    k3_mid<<<NPTS / 8, 192>>>(fts, dww, dwb);
    k4_pw<<<NPTS / 64, 256>>>();
    k5_stats<<<1, 256>>>();
    k6_norm<<<NPTS / 8, 256>>>(bng, bnb, out);
}